// round 1
// baseline (speedup 1.0000x reference)
#include <cuda_runtime.h>

// x: (4, 32, 512, 512) fp32 ; bias: (1, 32, 1, 1) fp32
// out: [G1 | G2 | G3], each (4, 32, 512, 512) fp32
//
// G1[h,w] = (h>=1 && w>=1) ? exp(-(x[h-1,w-1]-x[h,w])^2) + bias : bias
// G2[h,w] = (w>=1)          ? exp(-(x[h,  w-1]-x[h,w])^2) + bias : bias
// G3[h,w] = (h<H-1 && w>=1) ? exp(-(x[h+1,w-1]-x[h,w])^2) + bias : bias

#define H 512
#define W 512
#define WV (W / 4)          // 128 float4 per row
#define CHANS 32

__global__ __launch_bounds__(256) void embeded_gate_kernel(
    const float* __restrict__ x,
    const float* __restrict__ bias,
    float* __restrict__ out,
    long long n_elems)       // elements per gate tensor
{
    int idx = blockIdx.x * blockDim.x + threadIdx.x;
    // idx -> (bc, h, v)
    int v  = idx & (WV - 1);
    int h  = (idx >> 7) & (H - 1);
    int bc = idx >> 16;
    int c  = bc & (CHANS - 1);

    const float bi = __ldg(&bias[c]);

    const float4* __restrict__ x4 = reinterpret_cast<const float4*>(x);
    const long long row4 = (long long)bc * (H * WV) + (long long)h * WV;   // float4 index of row start
    const long long rowS = (long long)bc * (H * W)  + (long long)h * W;    // scalar index of row start
    const int w0 = v << 2;

    // current row
    float4 cur4 = x4[row4 + v];
    float cur[4] = {cur4.x, cur4.y, cur4.z, cur4.w};

    // left-shifted current row neighbors: {x[h][w0-1], cur.x, cur.y, cur.z}
    float lscal = (v > 0) ? __ldg(&x[rowS + w0 - 1]) : 0.0f;
    float lf[4] = {lscal, cur4.x, cur4.y, cur4.z};

    // row above (h-1), shifted left by 1
    float up[4] = {0.f, 0.f, 0.f, 0.f};
    if (h > 0) {
        float4 u4 = x4[row4 - WV + v];
        float ul = (v > 0) ? __ldg(&x[rowS - W + w0 - 1]) : 0.0f;
        up[0] = ul; up[1] = u4.x; up[2] = u4.y; up[3] = u4.z;
    }

    // row below (h+1), shifted left by 1
    float dn[4] = {0.f, 0.f, 0.f, 0.f};
    if (h < H - 1) {
        float4 d4 = x4[row4 + WV + v];
        float dl = (v > 0) ? __ldg(&x[rowS + W + w0 - 1]) : 0.0f;
        dn[0] = dl; dn[1] = d4.x; dn[2] = d4.y; dn[3] = d4.z;
    }

    float g1[4], g2[4], g3[4];
    const bool hup = (h > 0);
    const bool hdn = (h < H - 1);
#pragma unroll
    for (int k = 0; k < 4; ++k) {
        bool wok = (v > 0) || (k > 0);   // global w index > 0
        float d1 = up[k] - cur[k];
        float d2 = lf[k] - cur[k];
        float d3 = dn[k] - cur[k];
        g1[k] = (hup && wok) ? __expf(-d1 * d1) + bi : bi;
        g2[k] = (wok)        ? __expf(-d2 * d2) + bi : bi;
        g3[k] = (hdn && wok) ? __expf(-d3 * d3) + bi : bi;
    }

    float4* __restrict__ o4 = reinterpret_cast<float4*>(out);
    const long long n4 = n_elems >> 2;       // float4 count per gate
    const long long p = row4 + v;
    o4[p]          = make_float4(g1[0], g1[1], g1[2], g1[3]);
    o4[p + n4]     = make_float4(g2[0], g2[1], g2[2], g2[3]);
    o4[p + 2 * n4] = make_float4(g3[0], g3[1], g3[2], g3[3]);
}

extern "C" void kernel_launch(void* const* d_in, const int* in_sizes, int n_in,
                              void* d_out, int out_size) {
    const float* x    = (const float*)d_in[0];
    const float* bias = (const float*)d_in[1];
    float* out = (float*)d_out;

    const long long n_elems = (long long)in_sizes[0];          // 4*32*512*512
    const long long total_vec = n_elems / 4;                   // 8,388,608 threads
    const int threads = 256;
    const int blocks = (int)((total_vec + threads - 1) / threads);

    embeded_gate_kernel<<<blocks, threads>>>(x, bias, out, n_elems);
}